// round 14
// baseline (speedup 1.0000x reference)
#include <cuda_runtime.h>
#include <math.h>

#define COL 14
#define NJ 14
#define NPIX 196
#define NB 8192
#define NJOINT (NB * NJ)                   // 114688
#define THREADS 256
#define NWARPS 8
#define GRID 760                           // 152 SMs x 5 CTAs: single wave
#define WTOT (GRID * NWARPS)               // 6080 warps
#define NT4 (NJOINT / 4)                   // 28672 tasks of 4 joints
#define TEXTRA (NT4 - 4 * WTOT)            // 4352: warps below this do 5 tasks
#define SLOTS 3

struct GParams {
    float GT[NPIX];      // GT[c*14+r] = G[r][c]
    float T2[NPIX];      // sum ttn^2 per (yi,xi)
    float m2invT[NPIX];  // -2 * 1/(mx-mn)
    float m2nmiT[NPIX];  // -2 * (-mn/(mx-mn))
};

__device__ float    g_d1[GRID];
__device__ float    g_d2[GRID];
__device__ float    g_cnt[GRID];
__device__ unsigned g_ticket;   // zero-init at load; net-zero per run

// ---- packed f32x2 helpers ----
__device__ __forceinline__ unsigned long long pack2(float lo, float hi) {
    unsigned long long r;
    asm("mov.b64 %0,{%1,%2};" : "=l"(r) : "f"(lo), "f"(hi));
    return r;
}
__device__ __forceinline__ void unpack2(unsigned long long p, float& lo, float& hi) {
    asm("mov.b64 {%0,%1},%2;" : "=f"(lo), "=f"(hi) : "l"(p));
}
__device__ __forceinline__ unsigned long long mul2(unsigned long long a, unsigned long long b) {
    unsigned long long r;
    asm("mul.rn.f32x2 %0,%1,%2;" : "=l"(r) : "l"(a), "l"(b));
    return r;
}
__device__ __forceinline__ unsigned long long add2(unsigned long long a, unsigned long long b) {
    unsigned long long r;
    asm("add.rn.f32x2 %0,%1,%2;" : "=l"(r) : "l"(a), "l"(b));
    return r;
}
__device__ __forceinline__ unsigned long long fma2(unsigned long long a, unsigned long long b,
                                                   unsigned long long c) {
    unsigned long long r;
    asm("fma.rn.f32x2 %0,%1,%2,%3;" : "=l"(r) : "l"(a), "l"(b), "l"(c));
    return r;
}

#define CP_ASYNC16(dst_u32, src_ptr) \
    asm volatile("cp.async.cg.shared.global [%0], [%1], 16;" \
                 :: "r"(dst_u32), "l"(src_ptr) : "memory")
#define CP_COMMIT() asm volatile("cp.async.commit_group;" ::: "memory")
#define CP_WAIT(n)  asm volatile("cp.async.wait_group %0;" :: "n"(n) : "memory")

__global__ __launch_bounds__(THREADS, 5) void main_kernel(
    const float* __restrict__ outp,
    const float* __restrict__ t,
    const float* __restrict__ v,
    float* __restrict__ o,
    const GParams gp)
{
    __shared__ __align__(16) float sH[NWARPS * SLOTS * 2 * NPIX];   // 37632 B
    __shared__ __align__(16) float sGT[NPIX];
    __shared__ float sred[NWARPS][3];
    __shared__ int   sBidx[NWARPS][32];
    __shared__ int   s_last;
    __shared__ double dra[NWARPS], drb[NWARPS], drc[NWARPS];

    const int tid = threadIdx.x;
    if (tid < NPIX) sGT[tid] = gp.GT[tid];
    __syncthreads();

    const int lane = tid & 31;
    const int warp = tid >> 5;
    const int gwarp = blockIdx.x * NWARPS + warp;
    const bool hasB = lane < 17;
    const int base4 = 4 * lane;
    const int baseByte = 16 * lane;

    const int ntask = (gwarp < TEXTRA) ? 5 : 4;
    const int ng = 2 * ntask;            // groups of 2 joints

    const unsigned sHbase =
        (unsigned)__cvta_generic_to_shared(&sH[warp * (SLOTS * 2 * NPIX)]);
    const float* sHw = &sH[warp * (SLOTS * 2 * NPIX)];

    // ---- per-lane pair geometry ----
    int ybO[4], xbO[4];
    {
        #pragma unroll
        for (int p = 0; p < 4; ++p) {
            int e0 = (p < 2) ? (base4 + 2 * p) : (128 + base4 + 2 * (p - 2));
            if (p >= 2 && !hasB) e0 = 0;
            int y = e0 / COL;
            ybO[p] = y * 4;
            xbO[p] = (e0 - y * COL) * 4;
        }
    }

    // group gg -> first joint of the 2-joint pair
    auto group_joint0 = [&](int gg) {
        const int task = gg >> 1;
        return (gwarp + task * WTOT) * 4 + (gg & 1) * 2;
    };

    auto issue = [&](int gg, int slot) {
        const int j0 = group_joint0(gg);
        #pragma unroll
        for (int i = 0; i < 2; ++i) {
            const int joint = j0 + i;
            const int b2 = joint / NJ;
            const int j2 = joint - b2 * NJ;
            const char* hb = reinterpret_cast<const char*>(
                outp + ((size_t)b2 * (3 * NJ) + j2) * NPIX);
            const unsigned dst = sHbase + (slot * 2 + i) * (NPIX * 4);
            CP_ASYNC16(dst + baseByte, hb + baseByte);
            if (hasB) CP_ASYNC16(dst + 512 + baseByte, hb + 512 + baseByte);
        }
        CP_COMMIT();
    };

    float d1 = 0.0f;

    auto compute = [&](int gg, int slot) {
        const int j0 = group_joint0(gg);
        const int bslot = (gg >> 1) * 4 + (gg & 1) * 2;   // task-major, 4 joints/task
        const float4 tv = *reinterpret_cast<const float4*>(t + 2 * (size_t)j0);
        const float4 vv = *reinterpret_cast<const float4*>(v + 2 * (size_t)j0);
        #pragma unroll
        for (int i = 0; i < 2; ++i) {
            const float* sj = sHw + (slot * 2 + i) * NPIX;
            const float4 a = *reinterpret_cast<const float4*>(sj + base4);
            float4 b = make_float4(0.0f, 0.0f, 0.0f, 0.0f);
            if (hasB) b = *reinterpret_cast<const float4*>(sj + 128 + base4);

            const unsigned long long p01 = pack2(a.x, a.y);
            const unsigned long long p23 = pack2(a.z, a.w);
            const unsigned long long p45 = pack2(b.x, b.y);
            const unsigned long long p67 = pack2(b.z, b.w);

            unsigned long long s2 = fma2(p01, p01, mul2(p23, p23));
            s2 = fma2(p45, p45, s2);
            s2 = fma2(p67, p67, s2);
            float h2lo, h2hi; unpack2(s2, h2lo, h2hi);
            const float ph2 = h2lo + h2hi;

            const float t0 = i ? tv.z : tv.x;
            const float t1 = i ? tv.w : tv.y;
            const float v0 = i ? vv.z : vv.x;
            const int xi = (int)(t0 * 14.0f);
            const int yi = (int)(t1 * 14.0f);
            const bool inb = (xi >= 0) && (xi <= COL - 1) && (yi >= 0) && (yi <= COL - 1);
            const bool vis = ((int)v0) == 1;
            const bool scat = vis && inb;       // warp-uniform

            if (scat) {
                unsigned long long sh = add2(add2(p01, p23), add2(p45, p67));
                float shlo, shhi; unpack2(sh, shlo, shhi);
                const float ph = shlo + shhi;

                const char* gyrowB = reinterpret_cast<const char*>(sGT + yi * COL);
                const char* gxrowB = reinterpret_cast<const char*>(sGT + xi * COL);
                unsigned long long acc = 0ull;
                {
                    const float gy = *(const float*)(gyrowB + ybO[0]);
                    const unsigned long long gx2 = *(const unsigned long long*)(gxrowB + xbO[0]);
                    acc = fma2(mul2(gx2, p01), pack2(gy, gy), acc);
                }
                {
                    const float gy = *(const float*)(gyrowB + ybO[1]);
                    const unsigned long long gx2 = *(const unsigned long long*)(gxrowB + xbO[1]);
                    acc = fma2(mul2(gx2, p23), pack2(gy, gy), acc);
                }
                {
                    const float gy = *(const float*)(gyrowB + ybO[2]);
                    const unsigned long long gx2 = *(const unsigned long long*)(gxrowB + xbO[2]);
                    acc = fma2(mul2(gx2, p45), pack2(gy, gy), acc);
                }
                {
                    const float gy = *(const float*)(gyrowB + ybO[3]);
                    const unsigned long long gx2 = *(const unsigned long long*)(gxrowB + xbO[3]);
                    acc = fma2(mul2(gx2, p67), pack2(gy, gy), acc);
                }
                float htlo, hthi; unpack2(acc, htlo, hthi);
                const float phtt = htlo + hthi;

                const int cell = yi * COL + xi;     // warp-uniform -> LDC
                const float m2inv = gp.m2invT[cell];
                const float m2nmi = gp.m2nmiT[cell];

                d1 += fmaf(m2inv, phtt, fmaf(m2nmi, ph, ph2));
                if (lane == 0) d1 += gp.T2[cell];

                float best = fmaxf(fmaxf(a.x, a.y), fmaxf(a.z, a.w));
                if (hasB) best = fmaxf(best, fmaxf(fmaxf(b.x, b.y), fmaxf(b.z, b.w)));
                int idx = 0x7fffffff;
                if (hasB) {
                    idx = (b.w == best) ? (131 + base4) : idx;
                    idx = (b.z == best) ? (130 + base4) : idx;
                    idx = (b.y == best) ? (129 + base4) : idx;
                    idx = (b.x == best) ? (128 + base4) : idx;
                }
                idx = (a.w == best) ? (3 + base4) : idx;
                idx = (a.z == best) ? (2 + base4) : idx;
                idx = (a.y == best) ? (1 + base4) : idx;
                idx = (a.x == best) ? (base4) : idx;

                unsigned u = __float_as_uint(best);
                unsigned mono = ((int)u < 0) ? ~u : (u | 0x80000000u);
                unsigned mmax = __reduce_max_sync(0xffffffffu, mono);
                int cand = (mono == mmax) ? idx : 0x7fffffff;
                int bidx = __reduce_min_sync(0xffffffffu, cand);
                if (lane == 0) sBidx[warp][bslot + i] = bidx;
            } else {
                float pr = 0.0f;
                if (lane < 4) {
                    pr = fmaf(a.x, a.x, a.y * a.y);
                    if (lane < 3) pr += fmaf(a.z, a.z, a.w * a.w);
                }
                d1 += ph2 - pr;
            }
        }
    };

    // ---- continuous 3-slot pipeline over all ng groups ----
    issue(0, 0); issue(1, 1); issue(2, 2);
    {
        int slot = 0;
        for (int gg = 0; gg + 3 < ng; ++gg) {
            CP_WAIT(2);
            compute(gg, slot);
            issue(gg + 3, slot);
            slot = (slot == 2) ? 0 : slot + 1;
        }
        CP_WAIT(2); compute(ng - 3, slot); slot = (slot == 2) ? 0 : slot + 1;
        CP_WAIT(1); compute(ng - 2, slot); slot = (slot == 2) ? 0 : slot + 1;
        CP_WAIT(0); compute(ng - 1, slot);
    }

    // warp-reduce d1
    #pragma unroll
    for (int off = 16; off; off >>= 1)
        d1 += __shfl_xor_sync(0xffffffffu, d1, off);

    __syncwarp();

    // ---- phase B: one joint per lane (up to 20) ----
    float d2 = 0.0f, cntf = 0.0f;
    if (lane < ntask * 4) {
        const int joint = (gwarp + (lane >> 2) * WTOT) * 4 + (lane & 3);
        const float t0 = t[2 * joint];
        const float t1 = t[2 * joint + 1];
        const float v0 = v[2 * joint];
        const int xi = (int)(t0 * 14.0f);
        const int yi = (int)(t1 * 14.0f);
        const bool inb = (xi >= 0) && (xi <= COL - 1) && (yi >= 0) && (yi <= COL - 1);
        const bool vis = ((int)v0) == 1;
        const float vef = (vis && !inb) ? 0.0f : v0;
        const float veI = (((int)vef) == 1) ? 1.0f : 0.0f;
        cntf = veI;

        if (vis && inb) {
            const int b2 = joint / NJ;
            const int j2 = joint - b2 * NJ;
            const int bidx = sBidx[warp][lane];
            const size_t ob = (size_t)b2 * (3 * NJ) * NPIX;
            const float ox = outp[ob + (size_t)(NJ + j2) * NPIX + bidx];
            const float oy = outp[ob + (size_t)(2 * NJ + j2) * NPIX + bidx];
            const int yc = bidx / COL;
            const int xc = bidx - yc * COL;
            const float px = (ox + (float)xc) * (1.0f / 14.0f);
            const float py = (oy + (float)yc) * (1.0f / 14.0f);
            const float dx = (px - t0) * vef;
            const float dy = (py - t1) * vef;
            d2 = fmaf(dx, dx, dy * dy);
        }
    }
    #pragma unroll
    for (int off = 16; off; off >>= 1) {
        d2   += __shfl_xor_sync(0xffffffffu, d2, off);
        cntf += __shfl_xor_sync(0xffffffffu, cntf, off);
    }

    if (lane == 0) { sred[warp][0] = d1; sred[warp][1] = d2; sred[warp][2] = cntf; }
    __syncthreads();

    if (tid == 0) {
        float a = 0.0f, bsum = 0.0f, c = 0.0f;
        #pragma unroll
        for (int w = 0; w < NWARPS; ++w) { a += sred[w][0]; bsum += sred[w][1]; c += sred[w][2]; }
        g_d1[blockIdx.x] = a;
        g_d2[blockIdx.x] = bsum;
        g_cnt[blockIdx.x] = c;
        __threadfence();
        unsigned old = atomicAdd(&g_ticket, 1u);
        s_last = (old == GRID - 1);
    }
    __syncthreads();

    // ---- last block: grid reduction ----
    if (s_last) {
        if (tid == 0) g_ticket = 0;          // net-zero per run
        __threadfence();
        double a = 0.0, bsum = 0.0, c = 0.0;
        for (int i = tid; i < GRID; i += THREADS) {
            a    += (double)g_d1[i];
            bsum += (double)g_d2[i];
            c    += (double)g_cnt[i];
        }
        #pragma unroll
        for (int off = 16; off; off >>= 1) {
            a    += __shfl_xor_sync(0xffffffffu, a, off);
            bsum += __shfl_xor_sync(0xffffffffu, bsum, off);
            c    += __shfl_xor_sync(0xffffffffu, c, off);
        }
        if (lane == 0) { dra[warp] = a; drb[warp] = bsum; drc[warp] = c; }
        __syncthreads();
        if (tid == 0) {
            double A = 0.0, B = 0.0, C = 0.0;
            #pragma unroll
            for (int w = 0; w < NWARPS; ++w) { A += dra[w]; B += drb[w]; C += drc[w]; }
            o[0] = (float)(A / C + B / C);   // n2 == cnt (v is a tiled 0/1 mask)
        }
    }
}

extern "C" void kernel_launch(void* const* d_in, const int* in_sizes, int n_in,
                              void* d_out, int out_size)
{
    const float* outp = (const float*)d_in[0];
    const float* t    = (const float*)d_in[1];
    const float* v    = (const float*)d_in[2];

    GParams gp;
    {
        double w[9], ws = 0.0;
        for (int k = 0; k < 9; ++k) { w[k] = exp(-0.5 * (double)((k - 4) * (k - 4))); ws += w[k]; }
        for (int k = 0; k < 9; ++k) w[k] /= ws;
        for (int r = 0; r < COL; ++r)
            for (int c = 0; c < COL; ++c) {
                double s = 0.0;
                for (int k = 0; k < 9; ++k) {
                    int rr = r + k;   // padded row, pad=4, 'symmetric'
                    int m = (rr < 4) ? (3 - rr) : ((rr > 17) ? (31 - rr) : (rr - 4));
                    if (m == c) s += w[k];
                }
                gp.GT[c * COL + r] = (float)s;
            }
        float cmin[COL], cmax[COL];
        for (int c = 0; c < COL; ++c) {
            float mn = 1e30f, mx = -1e30f;
            for (int r = 0; r < COL; ++r) {
                float gv = gp.GT[c * COL + r];
                mn = fminf(mn, gv);
                mx = fmaxf(mx, gv);
            }
            cmin[c] = mn;
            cmax[c] = mx;
        }
        for (int yic = 0; yic < COL; ++yic)
            for (int xic = 0; xic < COL; ++xic) {
                float mn = cmin[yic] * cmin[xic];
                float mx = cmax[yic] * cmax[xic];
                double invd = 1.0 / ((double)mx - (double)mn);
                float inv = (float)invd;
                double s = 0.0;
                for (int y = 0; y < COL; ++y)
                    for (int x = 0; x < COL; ++x) {
                        float tt = gp.GT[yic * COL + y] * gp.GT[xic * COL + x];
                        float ttn = (tt - mn) * inv;
                        s += (double)ttn * (double)ttn;
                    }
                const int cell = yic * COL + xic;
                gp.T2[cell] = (float)s;
                gp.m2invT[cell] = -2.0f * inv;
                gp.m2nmiT[cell] = -2.0f * (-mn * inv);
            }
    }

    main_kernel<<<GRID, THREADS>>>(outp, t, v, (float*)d_out, gp);
}